// round 11
// baseline (speedup 1.0000x reference)
#include <cuda_runtime.h>
#include <cstdint>

#define BB   4
#define CCH  64
#define HH   180
#define WWD  320
#define HWP  (HH*WWD)
#define NPIX (BB*HWP)
#define NELT ((size_t)NPIX*CCH)

__device__ float g_QlT[(size_t)NPIX*CCH];   // [pix][c]
__device__ float g_Qr [(size_t)NPIX*CCH];   // [c][pix]
__device__ float g_Vl [(size_t)NPIX*CCH];   // [c][pix]
__device__ float g_Vr [(size_t)NPIX*CCH];   // [c][pix]

__device__ __forceinline__ uint32_t f2tf(float x){
    uint32_t u; asm("cvt.rna.tf32.f32 %0, %1;" : "=r"(u) : "f"(x)); return u;
}
__device__ __forceinline__ uint32_t pack_bf2(float lo, float hi){
    uint32_t u; asm("cvt.rn.bf16x2.f32 %0, %1, %2;" : "=r"(u) : "f"(hi), "f"(lo)); return u;
}
__device__ __forceinline__ uint32_t sptr(const void* p){
    return (uint32_t)__cvta_generic_to_shared(p);
}
__device__ __forceinline__ void mma_tf32(float d[4], const uint32_t a[4], const uint32_t b[2]){
    asm volatile("mma.sync.aligned.m16n8k8.row.col.f32.tf32.tf32.f32 "
                 "{%0,%1,%2,%3}, {%4,%5,%6,%7}, {%8,%9}, {%0,%1,%2,%3};"
                 : "+f"(d[0]), "+f"(d[1]), "+f"(d[2]), "+f"(d[3])
                 : "r"(a[0]), "r"(a[1]), "r"(a[2]), "r"(a[3]), "r"(b[0]), "r"(b[1]));
}
__device__ __forceinline__ void mma_bf16(float d[4], const uint32_t a[4], const uint32_t b[2]){
    asm volatile("mma.sync.aligned.m16n8k16.row.col.f32.bf16.bf16.f32 "
                 "{%0,%1,%2,%3}, {%4,%5,%6,%7}, {%8,%9}, {%0,%1,%2,%3};"
                 : "+f"(d[0]), "+f"(d[1]), "+f"(d[2]), "+f"(d[3])
                 : "r"(a[0]), "r"(a[1]), "r"(a[2]), "r"(a[3]), "r"(b[0]), "r"(b[1]));
}
__device__ __forceinline__ void ldsm4(uint32_t r[4], uint32_t a){
    asm volatile("ldmatrix.sync.aligned.m8n8.x4.shared.b16 {%0,%1,%2,%3}, [%4];"
        : "=r"(r[0]), "=r"(r[1]), "=r"(r[2]), "=r"(r[3]) : "r"(a));
}
__device__ __forceinline__ void ldsm4t(uint32_t r[4], uint32_t a){
    asm volatile("ldmatrix.sync.aligned.m8n8.x4.trans.shared.b16 {%0,%1,%2,%3}, [%4];"
        : "=r"(r[0]), "=r"(r[1]), "=r"(r[2]), "=r"(r[3]) : "r"(a));
}
__device__ __forceinline__ void ldsm2t(uint32_t r[2], uint32_t a){
    asm volatile("ldmatrix.sync.aligned.m8n8.x2.trans.shared.b16 {%0,%1}, [%2];"
        : "=r"(r[0]), "=r"(r[1]) : "r"(a));
}

// ---------------- projection via tensor cores, coalesced epilogues ----------------
__global__ __launch_bounds__(256) void proj_mma_kernel(
    const float* __restrict__ x_l, const float* __restrict__ x_r,
    const float* __restrict__ lnw_l, const float* __restrict__ lnb_l,
    const float* __restrict__ lnw_r, const float* __restrict__ lnb_r,
    const float* __restrict__ wq_l,  const float* __restrict__ bq_l,
    const float* __restrict__ wq_r,  const float* __restrict__ bq_r,
    const float* __restrict__ wv_l,  const float* __restrict__ bv_l,
    const float* __restrict__ wv_r,  const float* __restrict__ bv_r)
{
    extern __shared__ float smf[];
    float*    xs = smf;                         // [64][68]
    uint32_t* xt = (uint32_t*)(smf + 4352);     // [64][68]
    uint32_t* wA = (uint32_t*)(smf + 8704);     // [64][68]
    float*    mu_s = smf + 13056;
    float*    rs_s = smf + 13120;
    float*    stf  = (float*)xt;                // staging alias

    int side = blockIdx.x >= 3600;
    int blk  = blockIdx.x - side * 3600;

    const float* x   = side ? x_r   : x_l;
    const float* lnw = side ? lnw_r : lnw_l;
    const float* lnb = side ? lnb_r : lnb_l;
    const float* wq  = side ? wq_r  : wq_l;
    const float* bq  = side ? bq_r  : bq_l;
    const float* wv  = side ? wv_r  : wv_l;
    const float* bv  = side ? bv_r  : bv_l;
    float* Qo = side ? g_Qr : g_QlT;
    float* Vo = side ? g_Vr : g_Vl;

    int tid = threadIdx.x, lane = tid & 31, wid = tid >> 5;
    int pb  = blk * 64;
    int b   = pb / HWP;
    int q0  = pb - b * HWP;
    const float* xb = x + ((size_t)b * CCH) * HWP + q0;

    #pragma unroll
    for (int i = 0; i < 16; i++) {
        int idx = i * 256 + tid;
        int hi = idx >> 6, lo = idx & 63;
        xs[hi * 68 + lo] = xb[(size_t)hi * HWP + lo];
        wA[hi * 68 + lo] = f2tf(wv[idx]);
    }
    __syncthreads();

    if (tid < 64) {
        float s = 0.f, ss = 0.f;
        #pragma unroll
        for (int c = 0; c < 64; c++) { float v = xs[c * 68 + tid]; s += v; ss += v*v; }
        float m = s * 0.015625f;
        mu_s[tid] = m;
        rs_s[tid] = rsqrtf(ss * 0.015625f - m*m + 1e-6f);
    }
    #pragma unroll
    for (int i = 0; i < 16; i++) {
        int idx = i * 256 + tid;
        int c = idx >> 6, p = idx & 63;
        xt[c * 68 + p] = f2tf(xs[c * 68 + p]);
    }
    __syncthreads();

    int wy = wid >> 1, wx = wid & 1;
    int m0 = wy * 16, n0 = wx * 32;
    int g = lane >> 2, t = lane & 3;
    int r = m0 + g;

    // ---- V = wv @ x ----
    float Cv[4][4];
    #pragma unroll
    for (int nt = 0; nt < 4; nt++)
        #pragma unroll
        for (int k = 0; k < 4; k++) Cv[nt][k] = 0.f;
    #pragma unroll
    for (int ks = 0; ks < 8; ks++) {
        uint32_t a[4], bbr[2];
        const uint32_t* pA = wA + (m0 + g) * 68 + ks*8 + t;
        a[0]=pA[0]; a[1]=pA[8*68]; a[2]=pA[4]; a[3]=pA[8*68+4];
        #pragma unroll
        for (int nt = 0; nt < 4; nt++) {
            const uint32_t* pB = xt + (ks*8 + t) * 68 + n0 + nt*8 + g;
            bbr[0]=pB[0]; bbr[1]=pB[4*68];
            mma_tf32(Cv[nt], a, bbr);
        }
    }
    __syncthreads();               // xt raw free
    {   // stage V + bias into stf[c][p]
        float b0 = bv[r], b1 = bv[r + 8];
        #pragma unroll
        for (int nt = 0; nt < 4; nt++) {
            int p = n0 + nt*8 + 2*t;
            *(float2*)&stf[r*68 + p]       = make_float2(Cv[nt][0]+b0, Cv[nt][1]+b0);
            *(float2*)&stf[(r+8)*68 + p]   = make_float2(Cv[nt][2]+b1, Cv[nt][3]+b1);
        }
    }
    __syncthreads();
    #pragma unroll
    for (int i = 0; i < 4; i++) {   // coalesced [c][pix] write
        int e = i * 256 + tid, c = e >> 4, p4 = e & 15;
        *(float4*)&Vo[((size_t)(b*CCH + c)) * HWP + q0 + 4*p4] =
            *(const float4*)&stf[c*68 + 4*p4];
    }
    __syncthreads();               // stf free

    #pragma unroll
    for (int i = 0; i < 16; i++) {
        int idx = i * 256 + tid;
        wA[(idx >> 6) * 68 + (idx & 63)] = f2tf(wq[idx]);
    }
    #pragma unroll
    for (int i = 0; i < 16; i++) {
        int idx = i * 256 + tid;
        int c = idx >> 6, p = idx & 63;
        xt[c * 68 + p] = f2tf((xs[c * 68 + p] - mu_s[p]) * rs_s[p] * lnw[c] + lnb[c]);
    }
    __syncthreads();

    // ---- Q = wq @ LN(x) ----
    float Cq[4][4];
    #pragma unroll
    for (int nt = 0; nt < 4; nt++)
        #pragma unroll
        for (int k = 0; k < 4; k++) Cq[nt][k] = 0.f;
    #pragma unroll
    for (int ks = 0; ks < 8; ks++) {
        uint32_t a[4], bbr[2];
        const uint32_t* pA = wA + (m0 + g) * 68 + ks*8 + t;
        a[0]=pA[0]; a[1]=pA[8*68]; a[2]=pA[4]; a[3]=pA[8*68+4];
        #pragma unroll
        for (int nt = 0; nt < 4; nt++) {
            const uint32_t* pB = xt + (ks*8 + t) * 68 + n0 + nt*8 + g;
            bbr[0]=pB[0]; bbr[1]=pB[4*68];
            mma_tf32(Cq[nt], a, bbr);
        }
    }
    __syncthreads();               // xt free
    if (side == 1) {
        float b0 = bq[r], b1 = bq[r + 8];
        #pragma unroll
        for (int nt = 0; nt < 4; nt++) {
            int p = n0 + nt*8 + 2*t;
            *(float2*)&stf[r*68 + p]     = make_float2(Cq[nt][0]+b0, Cq[nt][1]+b0);
            *(float2*)&stf[(r+8)*68 + p] = make_float2(Cq[nt][2]+b1, Cq[nt][3]+b1);
        }
        __syncthreads();
        #pragma unroll
        for (int i = 0; i < 4; i++) {
            int e = i * 256 + tid, c = e >> 4, p4 = e & 15;
            *(float4*)&Qo[((size_t)(b*CCH + c)) * HWP + q0 + 4*p4] =
                *(const float4*)&stf[c*68 + 4*p4];
        }
    } else {
        #pragma unroll
        for (int nt = 0; nt < 4; nt++) {   // transpose stage [p][c]
            int p = n0 + nt*8 + 2*t;
            stf[p * 68 + r]           = Cq[nt][0];
            stf[(p + 1) * 68 + r]     = Cq[nt][1];
            stf[p * 68 + r + 8]       = Cq[nt][2];
            stf[(p + 1) * 68 + r + 8] = Cq[nt][3];
        }
        __syncthreads();
        #pragma unroll
        for (int i = 0; i < 4; i++) {
            int e = i * 256 + tid, p = e >> 4, c4 = e & 15;
            float4 v = *(const float4*)(stf + p * 68 + c4 * 4);
            float4 bb4 = *(const float4*)(bq + c4 * 4);
            *(float4*)&Qo[((size_t)pb + p) * 64 + c4 * 4] =
                make_float4(v.x + bb4.x, v.y + bb4.y, v.z + bb4.z, v.w + bb4.w);
        }
    }
}

// ---------------- flash fused attention: resident Qr/Vr, bf16 E, LDSM frags ----------------
#define SM_CS  0
#define SM_RS  320
#define SM_QR  384
#define SM_QA  (SM_QR + 64*328)     // 21376
#define SM_VR  (SM_QA + 64*68)      // 25728
#define SM_VLS (SM_VR + 64*164)     // 36224
#define SM_EB  (SM_VLS + 64*36)     // 38528
#define SM_TOTW (SM_EB + 64*164)    // 49024 words = 196096 B

__global__ __launch_bounds__(512, 1) void fused_flash2_kernel(
    const float* __restrict__ x_l, const float* __restrict__ x_r,
    const float* __restrict__ beta, const float* __restrict__ gamma,
    float* __restrict__ out_l, float* __restrict__ out_r)
{
    extern __shared__ float sm[];
    float*    cs   = sm + SM_CS;
    float*    rs   = sm + SM_RS;
    uint32_t* Qru  = (uint32_t*)(sm + SM_QR);
    uint32_t* Qau  = (uint32_t*)(sm + SM_QA);
    uint32_t* VrBw = (uint32_t*)(sm + SM_VR);
    uint32_t* VlBw = (uint32_t*)(sm + SM_VLS);
    uint32_t* Ew   = (uint32_t*)(sm + SM_EB);
    float*    Ef   = sm + SM_EB;

    int tid = threadIdx.x, lane = tid & 31, wid = tid >> 5;
    int g = lane >> 2, t = lane & 3;
    int grp = lane >> 3, r8 = lane & 7;
    int bh = blockIdx.x, b = bh / HH, h = bh - b * HH;
    size_t pixb = (size_t)b * HWP + h * WWD;
    size_t cmb  = (size_t)b * CCH * HWP + h * WWD;

    if (tid < 320) cs[tid] = 0.f;
    {
        const float* src = g_Qr + cmb;
        #pragma unroll
        for (int i = 0; i < 10; i++) {
            int e = i * 512 + tid, c = e / 80, w4 = e % 80;
            float4 v = *(const float4*)(src + (size_t)c * HWP + 4*w4);
            *(uint4*)(Qru + c * 328 + 4*w4) =
                make_uint4(f2tf(v.x), f2tf(v.y), f2tf(v.z), f2tf(v.w));
        }
        const float* srv = g_Vr + cmb;
        #pragma unroll
        for (int i = 0; i < 10; i++) {
            int e = i * 512 + tid, c = e / 80, w4 = e % 80;
            float4 v = *(const float4*)(srv + (size_t)c * HWP + 4*w4);
            *(uint2*)(VrBw + c * 164 + 2*w4) =
                make_uint2(pack_bf2(v.x, v.y), pack_bf2(v.z, v.w));
        }
    }

    int wy3 = wid & 1, wx3 = wid >> 1;
    float C3[2][5][4];
    #pragma unroll
    for (int mt = 0; mt < 2; mt++)
        #pragma unroll
        for (int nt = 0; nt < 5; nt++)
            #pragma unroll
            for (int k = 0; k < 4; k++) C3[mt][nt][k] = 0.f;

    for (int s = 0; s < 5; s++) {
        int wl0 = s * 64;

        if (tid < 64) rs[tid] = 0.f;
        {
            const float* src = g_QlT + (pixb + wl0) * 64;
            #pragma unroll
            for (int i = 0; i < 2; i++) {
                int e = i * 512 + tid, wl = e >> 4, c4 = e & 15;
                float4 v = *(const float4*)(src + (size_t)wl * 64 + 4*c4);
                *(uint4*)(Qau + wl * 68 + 4*c4) =
                    make_uint4(f2tf(v.x), f2tf(v.y), f2tf(v.z), f2tf(v.w));
            }
            const float* srv = g_Vl + cmb + wl0;
            #pragma unroll
            for (int i = 0; i < 2; i++) {
                int e = i * 512 + tid, c = e >> 4, w4 = e & 15;
                float4 v = *(const float4*)(srv + (size_t)c * HWP + 4*w4);
                *(uint2*)(VlBw + c * 36 + 2*w4) =
                    make_uint2(pack_bf2(v.x, v.y), pack_bf2(v.z, v.w));
            }
        }
        __syncthreads();   // (A)

        // ---- GEMM1 (tf32): E = exp(0.125 * Ql_strip @ Qr) ----
        {
            int wy1 = wid >> 3, wx1 = wid & 7;
            int m0 = wy1 * 32, n0 = wx1 * 40;
            float C1[2][5][4];
            #pragma unroll
            for (int mt = 0; mt < 2; mt++)
                #pragma unroll
                for (int nt = 0; nt < 5; nt++)
                    #pragma unroll
                    for (int k = 0; k < 4; k++) C1[mt][nt][k] = 0.f;
            #pragma unroll
            for (int ks = 0; ks < 8; ks++) {
                uint32_t a[2][4], bbr[2];
                #pragma unroll
                for (int mt = 0; mt < 2; mt++) {
                    const uint32_t* pA = Qau + (m0 + mt*16 + g) * 68 + ks*8 + t;
                    a[mt][0]=pA[0]; a[mt][1]=pA[8*68]; a[mt][2]=pA[4]; a[mt][3]=pA[8*68+4];
                }
                #pragma unroll
                for (int nt = 0; nt < 5; nt++) {
                    const uint32_t* pB = Qru + (ks*8 + t) * 328 + n0 + nt*8 + g;
                    bbr[0]=pB[0]; bbr[1]=pB[4*328];
                    #pragma unroll
                    for (int mt = 0; mt < 2; mt++) mma_tf32(C1[mt][nt], a[mt], bbr);
                }
            }
            float rsum[2][2];
            rsum[0][0]=rsum[0][1]=rsum[1][0]=rsum[1][1]=0.f;
            #pragma unroll
            for (int nt = 0; nt < 5; nt++) {
                float cv0 = 0.f, cv1 = 0.f;
                #pragma unroll
                for (int mt = 0; mt < 2; mt++) {
                    float e0 = __expf(C1[mt][nt][0]*0.125f);
                    float e1 = __expf(C1[mt][nt][1]*0.125f);
                    float e2 = __expf(C1[mt][nt][2]*0.125f);
                    float e3 = __expf(C1[mt][nt][3]*0.125f);
                    int row = m0 + mt*16 + g;
                    int cw  = wx1*20 + nt*4 + t;
                    Ew[row * 164 + cw]       = pack_bf2(e0, e1);
                    Ew[(row + 8) * 164 + cw] = pack_bf2(e2, e3);
                    rsum[mt][0] += e0 + e1;
                    rsum[mt][1] += e2 + e3;
                    cv0 += e0 + e2;
                    cv1 += e1 + e3;
                }
                cv0 += __shfl_xor_sync(~0u, cv0, 4);
                cv0 += __shfl_xor_sync(~0u, cv0, 8);
                cv0 += __shfl_xor_sync(~0u, cv0, 16);
                cv1 += __shfl_xor_sync(~0u, cv1, 4);
                cv1 += __shfl_xor_sync(~0u, cv1, 8);
                cv1 += __shfl_xor_sync(~0u, cv1, 16);
                if (g == 0) {
                    int col = n0 + nt*8 + 2*t;
                    atomicAdd(&cs[col], cv0);
                    atomicAdd(&cs[col + 1], cv1);
                }
            }
            #pragma unroll
            for (int mt = 0; mt < 2; mt++) {
                float s0 = rsum[mt][0], s1 = rsum[mt][1];
                s0 += __shfl_xor_sync(~0u, s0, 1); s0 += __shfl_xor_sync(~0u, s0, 2);
                s1 += __shfl_xor_sync(~0u, s1, 1); s1 += __shfl_xor_sync(~0u, s1, 2);
                if (t == 0) {
                    atomicAdd(&rs[m0 + mt*16 + g], s0);
                    atomicAdd(&rs[m0 + mt*16 + g + 8], s1);
                }
            }
        }
        __syncthreads();   // (B)

        // ---- GEMM2' (bf16, LDSM): F^T[c][wl] = Vr @ E^T, K=320 ----
        {
            int wy2 = wid >> 2, wx2 = wid & 3;
            int m0 = wy2 * 16, n0 = wx2 * 16;
            uint32_t aBase = sptr(VrBw) + (uint32_t)((m0 + r8 + 8*(grp&1))*656 + 16*(grp>>1));
            uint32_t bBase = sptr(Ew)   + (uint32_t)((n0 + r8 + 8*(grp>>1))*656 + 16*(grp&1));
            float C2[2][4];
            #pragma unroll
            for (int nt = 0; nt < 2; nt++)
                #pragma unroll
                for (int k = 0; k < 4; k++) C2[nt][k] = 0.f;
            #pragma unroll 5
            for (int ks = 0; ks < 20; ks++) {
                uint32_t a[4], bbv[4];
                ldsm4(a, aBase + ks*32);
                ldsm4(bbv, bBase + ks*32);
                mma_bf16(C2[0], a, bbv);
                mma_bf16(C2[1], a, bbv + 2);
            }
            const float* xl = x_l + cmb;
            float* ol = out_l + cmb;
            int c0 = m0 + g;
            float bt0 = beta[c0], bt1 = beta[c0 + 8];
            #pragma unroll
            for (int nt = 0; nt < 2; nt++) {
                int wl = n0 + nt*8 + 2*t;
                float ri0 = __fdividef(1.f, rs[wl]);
                float ri1 = __fdividef(1.f, rs[wl + 1]);
                float2 x0 = *(const float2*)(xl + (size_t)c0*HWP + wl0 + wl);
                *(float2*)(ol + (size_t)c0*HWP + wl0 + wl) = make_float2(
                    x0.x + bt0*ri0*C2[nt][0], x0.y + bt0*ri1*C2[nt][1]);
                float2 x1 = *(const float2*)(xl + (size_t)(c0+8)*HWP + wl0 + wl);
                *(float2*)(ol + (size_t)(c0+8)*HWP + wl0 + wl) = make_float2(
                    x1.x + bt1*ri0*C2[nt][2], x1.y + bt1*ri1*C2[nt][3]);
            }
        }

        // ---- GEMM3 (bf16, LDSM + trans): C3 += Vl_strip @ E ----
        {
            int m0 = wy3 * 32, n0 = wx3 * 40;
            uint32_t aBase  = sptr(VlBw) + (uint32_t)((m0 + r8 + 8*(grp&1))*144 + 16*(grp>>1));
            uint32_t bBase  = sptr(Ew) + (uint32_t)((r8 + 8*(grp&1))*656 + (n0 + 8*(grp>>1))*2);
            uint32_t b2Base = sptr(Ew) + (uint32_t)((r8 + 8*(grp&1))*656 + (n0 + 32)*2);
            #pragma unroll
            for (int ks = 0; ks < 4; ks++) {
                uint32_t a0[4], a1[4], bb0[4], bb1[4], bb2[2];
                ldsm4(a0, aBase + ks*32);
                ldsm4(a1, aBase + 16*144 + ks*32);
                ldsm4t(bb0, bBase + ks*10496);
                ldsm4t(bb1, bBase + 32 + ks*10496);
                ldsm2t(bb2, b2Base + ks*10496);
                mma_bf16(C3[0][0], a0, bb0);   mma_bf16(C3[0][1], a0, bb0 + 2);
                mma_bf16(C3[0][2], a0, bb1);   mma_bf16(C3[0][3], a0, bb1 + 2);
                mma_bf16(C3[0][4], a0, bb2);
                mma_bf16(C3[1][0], a1, bb0);   mma_bf16(C3[1][1], a1, bb0 + 2);
                mma_bf16(C3[1][2], a1, bb1);   mma_bf16(C3[1][3], a1, bb1 + 2);
                mma_bf16(C3[1][4], a1, bb2);
            }
        }
        __syncthreads();   // (C)
    }

    if (tid < 320) cs[tid] = __fdividef(1.f, cs[tid]);
    __syncthreads();

    {
        const float* xr = x_r + cmb;
        float* orr = out_r + cmb;
        int m0 = wy3 * 32, n0 = wx3 * 40;
        #pragma unroll
        for (int mt = 0; mt < 2; mt++) {
            int c0 = m0 + mt*16 + g;
            float g0 = gamma[c0], g1 = gamma[c0 + 8];
            #pragma unroll
            for (int nt = 0; nt < 5; nt++) {
                int col = n0 + nt*8 + 2*t;
                float ci0 = cs[col], ci1 = cs[col + 1];
                float2 x0 = *(const float2*)(xr + (size_t)c0*HWP + col);
                *(float2*)(orr + (size_t)c0*HWP + col) = make_float2(
                    x0.x + g0*ci0*C3[mt][nt][0], x0.y + g0*ci1*C3[mt][nt][1]);
                float2 x1 = *(const float2*)(xr + (size_t)(c0+8)*HWP + col);
                *(float2*)(orr + (size_t)(c0+8)*HWP + col) = make_float2(
                    x1.x + g1*ci0*C3[mt][nt][2], x1.y + g1*ci1*C3[mt][nt][3]);
            }
        }
    }
}

extern "C" void kernel_launch(void* const* d_in, const int* in_sizes, int n_in,
                              void* d_out, int out_size)
{
    const float* x_l    = (const float*)d_in[0];
    const float* x_r    = (const float*)d_in[1];
    const float* ln_l_w = (const float*)d_in[2];
    const float* ln_l_b = (const float*)d_in[3];
    const float* ln_r_w = (const float*)d_in[4];
    const float* ln_r_b = (const float*)d_in[5];
    const float* wq_l   = (const float*)d_in[6];
    const float* bq_l   = (const float*)d_in[7];
    const float* wq_r   = (const float*)d_in[8];
    const float* bq_r   = (const float*)d_in[9];
    const float* wv_l   = (const float*)d_in[10];
    const float* bv_l   = (const float*)d_in[11];
    const float* wv_r   = (const float*)d_in[12];
    const float* bv_r   = (const float*)d_in[13];
    const float* beta   = (const float*)d_in[14];
    const float* gamma  = (const float*)d_in[15];

    float* out_l = (float*)d_out;
    float* out_r = out_l + NELT;

    cudaFuncSetAttribute(proj_mma_kernel,
                         cudaFuncAttributeMaxDynamicSharedMemorySize, 52736);
    cudaFuncSetAttribute(fused_flash2_kernel,
                         cudaFuncAttributeMaxDynamicSharedMemorySize, SM_TOTW*4);

    proj_mma_kernel<<<7200, 256, 52736>>>(
        x_l, x_r, ln_l_w, ln_l_b, ln_r_w, ln_r_b,
        wq_l, bq_l, wq_r, bq_r, wv_l, bv_l, wv_r, bv_r);
    fused_flash2_kernel<<<BB*HH, 512, SM_TOTW*4>>>(x_l, x_r, beta, gamma, out_l, out_r);
}

// round 12
// speedup vs baseline: 1.1534x; 1.1534x over previous
#include <cuda_runtime.h>
#include <cstdint>

#define BB   4
#define CCH  64
#define HH   180
#define WWD  320
#define HWP  (HH*WWD)
#define NPIX (BB*HWP)
#define NELT ((size_t)NPIX*CCH)

// bf16 scratch (stored as uint32 pairs)
__device__ uint32_t g_QlT[(size_t)NPIX*CCH/2];   // [pix][c]
__device__ uint32_t g_Qr [(size_t)NPIX*CCH/2];   // [c][pix]
__device__ uint32_t g_Vl [(size_t)NPIX*CCH/2];   // [c][pix]
__device__ uint32_t g_Vr [(size_t)NPIX*CCH/2];   // [c][pix]

__device__ __forceinline__ uint32_t f2tf(float x){
    uint32_t u; asm("cvt.rna.tf32.f32 %0, %1;" : "=r"(u) : "f"(x)); return u;
}
__device__ __forceinline__ uint32_t pack_bf2(float lo, float hi){
    uint32_t u; asm("cvt.rn.bf16x2.f32 %0, %1, %2;" : "=r"(u) : "f"(hi), "f"(lo)); return u;
}
__device__ __forceinline__ uint32_t sptr(const void* p){
    return (uint32_t)__cvta_generic_to_shared(p);
}
__device__ __forceinline__ void mma_tf32(float d[4], const uint32_t a[4], const uint32_t b[2]){
    asm volatile("mma.sync.aligned.m16n8k8.row.col.f32.tf32.tf32.f32 "
                 "{%0,%1,%2,%3}, {%4,%5,%6,%7}, {%8,%9}, {%0,%1,%2,%3};"
                 : "+f"(d[0]), "+f"(d[1]), "+f"(d[2]), "+f"(d[3])
                 : "r"(a[0]), "r"(a[1]), "r"(a[2]), "r"(a[3]), "r"(b[0]), "r"(b[1]));
}
__device__ __forceinline__ void mma_bf16(float d[4], const uint32_t a[4], const uint32_t b[2]){
    asm volatile("mma.sync.aligned.m16n8k16.row.col.f32.bf16.bf16.f32 "
                 "{%0,%1,%2,%3}, {%4,%5,%6,%7}, {%8,%9}, {%0,%1,%2,%3};"
                 : "+f"(d[0]), "+f"(d[1]), "+f"(d[2]), "+f"(d[3])
                 : "r"(a[0]), "r"(a[1]), "r"(a[2]), "r"(a[3]), "r"(b[0]), "r"(b[1]));
}
__device__ __forceinline__ void ldsm4(uint32_t r[4], uint32_t a){
    asm volatile("ldmatrix.sync.aligned.m8n8.x4.shared.b16 {%0,%1,%2,%3}, [%4];"
        : "=r"(r[0]), "=r"(r[1]), "=r"(r[2]), "=r"(r[3]) : "r"(a));
}
__device__ __forceinline__ void ldsm4t(uint32_t r[4], uint32_t a){
    asm volatile("ldmatrix.sync.aligned.m8n8.x4.trans.shared.b16 {%0,%1,%2,%3}, [%4];"
        : "=r"(r[0]), "=r"(r[1]), "=r"(r[2]), "=r"(r[3]) : "r"(a));
}
__device__ __forceinline__ void ldsm2t(uint32_t r[2], uint32_t a){
    asm volatile("ldmatrix.sync.aligned.m8n8.x2.trans.shared.b16 {%0,%1}, [%2];"
        : "=r"(r[0]), "=r"(r[1]) : "r"(a));
}

// ---------------- projection (tf32 mma, bf16 outputs) ----------------
__global__ __launch_bounds__(256) void proj_mma_kernel(
    const float* __restrict__ x_l, const float* __restrict__ x_r,
    const float* __restrict__ lnw_l, const float* __restrict__ lnb_l,
    const float* __restrict__ lnw_r, const float* __restrict__ lnb_r,
    const float* __restrict__ wq_l,  const float* __restrict__ bq_l,
    const float* __restrict__ wq_r,  const float* __restrict__ bq_r,
    const float* __restrict__ wv_l,  const float* __restrict__ bv_l,
    const float* __restrict__ wv_r,  const float* __restrict__ bv_r)
{
    extern __shared__ float smf[];
    float*    xs = smf;                         // [64][68]
    uint32_t* xt = (uint32_t*)(smf + 4352);     // [64][68]
    uint32_t* wA = (uint32_t*)(smf + 8704);     // [64][68]
    float*    mu_s = smf + 13056;
    float*    rs_s = smf + 13120;
    float*    stf  = (float*)xt;                // staging alias

    int side = blockIdx.x >= 3600;
    int blk  = blockIdx.x - side * 3600;

    const float* x   = side ? x_r   : x_l;
    const float* lnw = side ? lnw_r : lnw_l;
    const float* lnb = side ? lnb_r : lnb_l;
    const float* wq  = side ? wq_r  : wq_l;
    const float* bq  = side ? bq_r  : bq_l;
    const float* wv  = side ? wv_r  : wv_l;
    const float* bv  = side ? bv_r  : bv_l;
    uint32_t* Qo = side ? g_Qr : g_QlT;
    uint32_t* Vo = side ? g_Vr : g_Vl;

    int tid = threadIdx.x, lane = tid & 31, wid = tid >> 5;
    int pb  = blk * 64;
    int b   = pb / HWP;
    int q0  = pb - b * HWP;
    const float* xb = x + ((size_t)b * CCH) * HWP + q0;

    #pragma unroll
    for (int i = 0; i < 16; i++) {
        int idx = i * 256 + tid;
        int hi = idx >> 6, lo = idx & 63;
        xs[hi * 68 + lo] = xb[(size_t)hi * HWP + lo];
        wA[hi * 68 + lo] = f2tf(wv[idx]);
    }
    __syncthreads();

    if (tid < 64) {
        float s = 0.f, ss = 0.f;
        #pragma unroll
        for (int c = 0; c < 64; c++) { float v = xs[c * 68 + tid]; s += v; ss += v*v; }
        float m = s * 0.015625f;
        mu_s[tid] = m;
        rs_s[tid] = rsqrtf(ss * 0.015625f - m*m + 1e-6f);
    }
    #pragma unroll
    for (int i = 0; i < 16; i++) {
        int idx = i * 256 + tid;
        int c = idx >> 6, p = idx & 63;
        xt[c * 68 + p] = f2tf(xs[c * 68 + p]);
    }
    __syncthreads();

    int wy = wid >> 1, wx = wid & 1;
    int m0 = wy * 16, n0 = wx * 32;
    int g = lane >> 2, t = lane & 3;
    int r = m0 + g;

    // ---- V = wv @ x ----
    float Cv[4][4];
    #pragma unroll
    for (int nt = 0; nt < 4; nt++)
        #pragma unroll
        for (int k = 0; k < 4; k++) Cv[nt][k] = 0.f;
    #pragma unroll
    for (int ks = 0; ks < 8; ks++) {
        uint32_t a[4], bbr[2];
        const uint32_t* pA = wA + (m0 + g) * 68 + ks*8 + t;
        a[0]=pA[0]; a[1]=pA[8*68]; a[2]=pA[4]; a[3]=pA[8*68+4];
        #pragma unroll
        for (int nt = 0; nt < 4; nt++) {
            const uint32_t* pB = xt + (ks*8 + t) * 68 + n0 + nt*8 + g;
            bbr[0]=pB[0]; bbr[1]=pB[4*68];
            mma_tf32(Cv[nt], a, bbr);
        }
    }
    __syncthreads();
    {   // stage V + bias into stf[c][p]
        float b0 = bv[r], b1 = bv[r + 8];
        #pragma unroll
        for (int nt = 0; nt < 4; nt++) {
            int p = n0 + nt*8 + 2*t;
            *(float2*)&stf[r*68 + p]       = make_float2(Cv[nt][0]+b0, Cv[nt][1]+b0);
            *(float2*)&stf[(r+8)*68 + p]   = make_float2(Cv[nt][2]+b1, Cv[nt][3]+b1);
        }
    }
    __syncthreads();
    #pragma unroll
    for (int i = 0; i < 4; i++) {   // coalesced bf16 [c][pix] write
        int e = i * 256 + tid, c = e >> 4, p4 = e & 15;
        float4 v = *(const float4*)&stf[c*68 + 4*p4];
        ((uint2*)Vo)[(((size_t)(b*CCH + c)) * HWP + q0) / 4 + p4] =
            make_uint2(pack_bf2(v.x, v.y), pack_bf2(v.z, v.w));
    }
    __syncthreads();

    #pragma unroll
    for (int i = 0; i < 16; i++) {
        int idx = i * 256 + tid;
        wA[(idx >> 6) * 68 + (idx & 63)] = f2tf(wq[idx]);
    }
    #pragma unroll
    for (int i = 0; i < 16; i++) {
        int idx = i * 256 + tid;
        int c = idx >> 6, p = idx & 63;
        xt[c * 68 + p] = f2tf((xs[c * 68 + p] - mu_s[p]) * rs_s[p] * lnw[c] + lnb[c]);
    }
    __syncthreads();

    // ---- Q = wq @ LN(x) ----
    float Cq[4][4];
    #pragma unroll
    for (int nt = 0; nt < 4; nt++)
        #pragma unroll
        for (int k = 0; k < 4; k++) Cq[nt][k] = 0.f;
    #pragma unroll
    for (int ks = 0; ks < 8; ks++) {
        uint32_t a[4], bbr[2];
        const uint32_t* pA = wA + (m0 + g) * 68 + ks*8 + t;
        a[0]=pA[0]; a[1]=pA[8*68]; a[2]=pA[4]; a[3]=pA[8*68+4];
        #pragma unroll
        for (int nt = 0; nt < 4; nt++) {
            const uint32_t* pB = xt + (ks*8 + t) * 68 + n0 + nt*8 + g;
            bbr[0]=pB[0]; bbr[1]=pB[4*68];
            mma_tf32(Cq[nt], a, bbr);
        }
    }
    __syncthreads();
    if (side == 1) {
        float b0 = bq[r], b1 = bq[r + 8];
        #pragma unroll
        for (int nt = 0; nt < 4; nt++) {
            int p = n0 + nt*8 + 2*t;
            *(float2*)&stf[r*68 + p]     = make_float2(Cq[nt][0]+b0, Cq[nt][1]+b0);
            *(float2*)&stf[(r+8)*68 + p] = make_float2(Cq[nt][2]+b1, Cq[nt][3]+b1);
        }
        __syncthreads();
        #pragma unroll
        for (int i = 0; i < 4; i++) {
            int e = i * 256 + tid, c = e >> 4, p4 = e & 15;
            float4 v = *(const float4*)&stf[c*68 + 4*p4];
            ((uint2*)Qo)[(((size_t)(b*CCH + c)) * HWP + q0) / 4 + p4] =
                make_uint2(pack_bf2(v.x, v.y), pack_bf2(v.z, v.w));
        }
    } else {
        #pragma unroll
        for (int nt = 0; nt < 4; nt++) {   // transpose stage [p][c]
            int p = n0 + nt*8 + 2*t;
            stf[p * 68 + r]           = Cq[nt][0];
            stf[(p + 1) * 68 + r]     = Cq[nt][1];
            stf[p * 68 + r + 8]       = Cq[nt][2];
            stf[(p + 1) * 68 + r + 8] = Cq[nt][3];
        }
        __syncthreads();
        #pragma unroll
        for (int i = 0; i < 4; i++) {
            int e = i * 256 + tid, p = e >> 4, c4 = e & 15;
            float4 v = *(const float4*)(stf + p * 68 + c4 * 4);
            float4 bb4 = *(const float4*)(bq + c4 * 4);
            ((uint2*)Qo)[(size_t)(pb + p) * 16 + c4] = make_uint2(
                pack_bf2(v.x + bb4.x, v.y + bb4.y),
                pack_bf2(v.z + bb4.z, v.w + bb4.w));
        }
    }
}

// ---------------- fused attention: all-bf16 mma, double-buffered strips ----------------
// words: cs[320] rs[2][64] | Qr[64][164] | Vr[64][164] | E[64][164] | Qa[2][64][36] | Vl[2][64][36]
#define SM_CS   0
#define SM_RSA  320
#define SM_QR   448
#define SM_VR   (SM_QR + 64*164)     // 10944
#define SM_EB   (SM_VR + 64*164)     // 21440
#define SM_QA   (SM_EB + 64*164)     // 31936
#define SM_VL   (SM_QA + 2*64*36)    // 36544
#define SM_TOTW (SM_VL + 2*64*36)    // 41152 words = 164608 B

__global__ __launch_bounds__(512, 1) void fused_flash3_kernel(
    const float* __restrict__ x_l, const float* __restrict__ x_r,
    const float* __restrict__ beta, const float* __restrict__ gamma,
    float* __restrict__ out_l, float* __restrict__ out_r)
{
    extern __shared__ float sm[];
    float*    cs   = sm + SM_CS;
    float*    rsA  = sm + SM_RSA;             // [2][64]
    uint32_t* Qru  = (uint32_t*)(sm + SM_QR);
    uint32_t* VrBw = (uint32_t*)(sm + SM_VR);
    uint32_t* Ew   = (uint32_t*)(sm + SM_EB);
    uint32_t* QaB  = (uint32_t*)(sm + SM_QA); // [2][64][36]
    uint32_t* VlB  = (uint32_t*)(sm + SM_VL); // [2][64][36]

    int tid = threadIdx.x, lane = tid & 31, wid = tid >> 5;
    int g = lane >> 2, t = lane & 3;
    int grp = lane >> 3, r8 = lane & 7;
    int bh = blockIdx.x, b = bh / HH, h = bh - b * HH;
    size_t pixb = (size_t)b * HWP + h * WWD;
    size_t cmb  = (size_t)b * CCH * HWP + h * WWD;

    if (tid < 320) cs[tid] = 0.f;
    if (tid < 64) rsA[tid] = 0.f;

    // Qr, Vr resident (bf16 copies, 5 iters each)
    {
        const uint4* srq = (const uint4*)g_Qr;
        const uint4* srv = (const uint4*)g_Vr;
        #pragma unroll
        for (int i = 0; i < 5; i++) {
            int e = i * 512 + tid, c = e / 40, w8 = e % 40;
            size_t gi = (cmb + (size_t)c * HWP) / 8 + w8;
            *(uint4*)(Qru  + c * 164 + 4*w8) = srq[gi];
            *(uint4*)(VrBw + c * 164 + 4*w8) = srv[gi];
        }
    }
    // strip 0: Qa, Vl into buffer 0
    {
        const uint4* sq = (const uint4*)g_QlT;
        const uint4* sv = (const uint4*)g_Vl;
        int wl = tid >> 3, w8 = tid & 7;
        *(uint4*)(QaB + wl * 36 + 4*w8) = sq[(pixb + wl) * 8 + w8];
        *(uint4*)(VlB + wl * 36 + 4*w8) = sv[(cmb + (size_t)wl * HWP) / 8 + w8];
    }

    int wy3 = wid & 1, wx3 = wid >> 1;
    float C3[2][5][4];
    #pragma unroll
    for (int mt = 0; mt < 2; mt++)
        #pragma unroll
        for (int nt = 0; nt < 5; nt++)
            #pragma unroll
            for (int k = 0; k < 4; k++) C3[mt][nt][k] = 0.f;

    __syncthreads();   // (A0)

    for (int s = 0; s < 5; s++) {
        int wl0 = s * 64;
        int par = s & 1;
        uint32_t* Qau  = QaB + par * 2304;
        uint32_t* VlBw = VlB + par * 2304;
        float* rs = rsA + par * 64;

        // ---- GEMM1 (bf16, LDSM): E = exp(0.125 * Ql_strip @ Qr) ----
        {
            int wy1 = wid >> 3, wx1 = wid & 7;
            int m0 = wy1 * 32, n0 = wx1 * 40;
            uint32_t aBase  = sptr(Qau) + (uint32_t)((m0 + r8 + 8*(grp&1))*144 + 16*(grp>>1));
            uint32_t bBase  = sptr(Qru) + (uint32_t)((r8 + 8*(grp&1))*656 + (n0 + 8*(grp>>1))*2);
            uint32_t b2Base = sptr(Qru) + (uint32_t)((r8 + 8*(grp&1))*656 + (n0 + 32)*2);
            float C1[2][5][4];
            #pragma unroll
            for (int mt = 0; mt < 2; mt++)
                #pragma unroll
                for (int nt = 0; nt < 5; nt++)
                    #pragma unroll
                    for (int k = 0; k < 4; k++) C1[mt][nt][k] = 0.f;
            #pragma unroll
            for (int ks = 0; ks < 4; ks++) {
                uint32_t a0[4], a1[4], bb0[4], bb1[4], bb2[2];
                ldsm4(a0, aBase + ks*32);
                ldsm4(a1, aBase + 16*144 + ks*32);
                ldsm4t(bb0, bBase + ks*10496);
                ldsm4t(bb1, bBase + 32 + ks*10496);
                ldsm2t(bb2, b2Base + ks*10496);
                mma_bf16(C1[0][0], a0, bb0);   mma_bf16(C1[0][1], a0, bb0 + 2);
                mma_bf16(C1[0][2], a0, bb1);   mma_bf16(C1[0][3], a0, bb1 + 2);
                mma_bf16(C1[0][4], a0, bb2);
                mma_bf16(C1[1][0], a1, bb0);   mma_bf16(C1[1][1], a1, bb0 + 2);
                mma_bf16(C1[1][2], a1, bb1);   mma_bf16(C1[1][3], a1, bb1 + 2);
                mma_bf16(C1[1][4], a1, bb2);
            }
            float rsum[2][2];
            rsum[0][0]=rsum[0][1]=rsum[1][0]=rsum[1][1]=0.f;
            #pragma unroll
            for (int nt = 0; nt < 5; nt++) {
                float cv0 = 0.f, cv1 = 0.f;
                #pragma unroll
                for (int mt = 0; mt < 2; mt++) {
                    float e0 = __expf(C1[mt][nt][0]*0.125f);
                    float e1 = __expf(C1[mt][nt][1]*0.125f);
                    float e2 = __expf(C1[mt][nt][2]*0.125f);
                    float e3 = __expf(C1[mt][nt][3]*0.125f);
                    int row = m0 + mt*16 + g;
                    int cw  = wx1*20 + nt*4 + t;
                    Ew[row * 164 + cw]       = pack_bf2(e0, e1);
                    Ew[(row + 8) * 164 + cw] = pack_bf2(e2, e3);
                    rsum[mt][0] += e0 + e1;
                    rsum[mt][1] += e2 + e3;
                    cv0 += e0 + e2;
                    cv1 += e1 + e3;
                }
                cv0 += __shfl_xor_sync(~0u, cv0, 4);
                cv0 += __shfl_xor_sync(~0u, cv0, 8);
                cv0 += __shfl_xor_sync(~0u, cv0, 16);
                cv1 += __shfl_xor_sync(~0u, cv1, 4);
                cv1 += __shfl_xor_sync(~0u, cv1, 8);
                cv1 += __shfl_xor_sync(~0u, cv1, 16);
                if (g == 0) {
                    int col = n0 + nt*8 + 2*t;
                    atomicAdd(&cs[col], cv0);
                    atomicAdd(&cs[col + 1], cv1);
                }
            }
            #pragma unroll
            for (int mt = 0; mt < 2; mt++) {
                float s0 = rsum[mt][0], s1 = rsum[mt][1];
                s0 += __shfl_xor_sync(~0u, s0, 1); s0 += __shfl_xor_sync(~0u, s0, 2);
                s1 += __shfl_xor_sync(~0u, s1, 1); s1 += __shfl_xor_sync(~0u, s1, 2);
                if (t == 0) {
                    atomicAdd(&rs[m0 + mt*16 + g], s0);
                    atomicAdd(&rs[m0 + mt*16 + g + 8], s1);
                }
            }
        }
        __syncthreads();   // (B) E + rs ready

        // prefetch strip s+1 into other buffers; zero other rs
        if (s < 4) {
            uint32_t* Qan = QaB + (par^1) * 2304;
            uint32_t* Vln = VlB + (par^1) * 2304;
            const uint4* sq = (const uint4*)g_QlT;
            const uint4* sv = (const uint4*)g_Vl;
            int wl = tid >> 3, w8 = tid & 7;
            *(uint4*)(Qan + wl * 36 + 4*w8) = sq[(pixb + wl0 + 64 + wl) * 8 + w8];
            *(uint4*)(Vln + wl * 36 + 4*w8) = sv[(cmb + wl0 + 64 + (size_t)wl * HWP) / 8 + w8];
            if (tid < 64) rsA[(par^1)*64 + tid] = 0.f;
        }

        // ---- GEMM2' (bf16, LDSM): F^T[c][wl] = Vr @ E^T, K=320 ----
        {
            int wy2 = wid >> 2, wx2 = wid & 3;
            int m0 = wy2 * 16, n0 = wx2 * 16;
            uint32_t aBase = sptr(VrBw) + (uint32_t)((m0 + r8 + 8*(grp&1))*656 + 16*(grp>>1));
            uint32_t bBase = sptr(Ew)   + (uint32_t)((n0 + r8 + 8*(grp>>1))*656 + 16*(grp&1));
            float C2[2][4];
            #pragma unroll
            for (int nt = 0; nt < 2; nt++)
                #pragma unroll
                for (int k = 0; k < 4; k++) C2[nt][k] = 0.f;
            #pragma unroll 5
            for (int ks = 0; ks < 20; ks++) {
                uint32_t a[4], bbv[4];
                ldsm4(a, aBase + ks*32);
                ldsm4(bbv, bBase + ks*32);
                mma_bf16(C2[0], a, bbv);
                mma_bf16(C2[1], a, bbv + 2);
            }
            const float* xl = x_l + cmb;
            float* ol = out_l + cmb;
            int c0 = m0 + g;
            float bt0 = beta[c0], bt1 = beta[c0 + 8];
            #pragma unroll
            for (int nt = 0; nt < 2; nt++) {
                int wl = n0 + nt*8 + 2*t;
                float ri0 = __fdividef(1.f, rs[wl]);
                float ri1 = __fdividef(1.f, rs[wl + 1]);
                float2 x0 = *(const float2*)(xl + (size_t)c0*HWP + wl0 + wl);
                *(float2*)(ol + (size_t)c0*HWP + wl0 + wl) = make_float2(
                    x0.x + bt0*ri0*C2[nt][0], x0.y + bt0*ri1*C2[nt][1]);
                float2 x1 = *(const float2*)(xl + (size_t)(c0+8)*HWP + wl0 + wl);
                *(float2*)(ol + (size_t)(c0+8)*HWP + wl0 + wl) = make_float2(
                    x1.x + bt1*ri0*C2[nt][2], x1.y + bt1*ri1*C2[nt][3]);
            }
        }

        // ---- GEMM3 (bf16, LDSM + trans): C3 += Vl_strip @ E ----
        {
            int m0 = wy3 * 32, n0 = wx3 * 40;
            uint32_t aBase  = sptr(VlBw) + (uint32_t)((m0 + r8 + 8*(grp&1))*144 + 16*(grp>>1));
            uint32_t bBase  = sptr(Ew) + (uint32_t)((r8 + 8*(grp&1))*656 + (n0 + 8*(grp>>1))*2);
            uint32_t b2Base = sptr(Ew) + (uint32_t)((r8 + 8*(grp&1))*656 + (n0 + 32)*2);
            #pragma unroll
            for (int ks = 0; ks < 4; ks++) {
                uint32_t a0[4], a1[4], bb0[4], bb1[4], bb2[2];
                ldsm4(a0, aBase + ks*32);
                ldsm4(a1, aBase + 16*144 + ks*32);
                ldsm4t(bb0, bBase + ks*10496);
                ldsm4t(bb1, bBase + 32 + ks*10496);
                ldsm2t(bb2, b2Base + ks*10496);
                mma_bf16(C3[0][0], a0, bb0);   mma_bf16(C3[0][1], a0, bb0 + 2);
                mma_bf16(C3[0][2], a0, bb1);   mma_bf16(C3[0][3], a0, bb1 + 2);
                mma_bf16(C3[0][4], a0, bb2);
                mma_bf16(C3[1][0], a1, bb0);   mma_bf16(C3[1][1], a1, bb0 + 2);
                mma_bf16(C3[1][2], a1, bb1);   mma_bf16(C3[1][3], a1, bb1 + 2);
                mma_bf16(C3[1][4], a1, bb2);
            }
        }
        __syncthreads();   // (A) strip done; prefetch visible; E free
    }

    if (tid < 320) cs[tid] = __fdividef(1.f, cs[tid]);
    __syncthreads();

    {
        const float* xr = x_r + cmb;
        float* orr = out_r + cmb;
        int m0 = wy3 * 32, n0 = wx3 * 40;
        #pragma unroll
        for (int mt = 0; mt < 2; mt++) {
            int c0 = m0 + mt*16 + g;
            float g0 = gamma[c0], g1 = gamma[c0 + 8];
            #pragma unroll
            for (int nt = 0; nt < 5; nt++) {
                int col = n0 + nt*8 + 2*t;
                float ci0 = cs[col], ci1 = cs[col + 1];
                float2 x0 = *(const float2*)(xr + (size_t)c0*HWP + col);
                *(float2*)(orr + (size_t)c0*HWP + col) = make_float2(
                    x0.x + g0*ci0*C3[mt][nt][0], x0.y + g0*ci1*C3[mt][nt][1]);
                float2 x1 = *(const float2*)(xr + (size_t)(c0+8)*HWP + col);
                *(float2*)(orr + (size_t)(c0+8)*HWP + col) = make_float2(
                    x1.x + g1*ci0*C3[mt][nt][2], x1.y + g1*ci1*C3[mt][nt][3]);
            }
        }
    }
}

extern "C" void kernel_launch(void* const* d_in, const int* in_sizes, int n_in,
                              void* d_out, int out_size)
{
    const float* x_l    = (const float*)d_in[0];
    const float* x_r    = (const float*)d_in[1];
    const float* ln_l_w = (const float*)d_in[2];
    const float* ln_l_b = (const float*)d_in[3];
    const float* ln_r_w = (const float*)d_in[4];
    const float* ln_r_b = (const float*)d_in[5];
    const float* wq_l   = (const float*)d_in[6];
    const float* bq_l   = (const float*)d_in[7];
    const float* wq_r   = (const float*)d_in[8];
    const float* bq_r   = (const float*)d_in[9];
    const float* wv_l   = (const float*)d_in[10];
    const float* bv_l   = (const float*)d_in[11];
    const float* wv_r   = (const float*)d_in[12];
    const float* bv_r   = (const float*)d_in[13];
    const float* beta   = (const float*)d_in[14];
    const float* gamma  = (const float*)d_in[15];

    float* out_l = (float*)d_out;
    float* out_r = out_l + NELT;

    cudaFuncSetAttribute(proj_mma_kernel,
                         cudaFuncAttributeMaxDynamicSharedMemorySize, 52736);
    cudaFuncSetAttribute(fused_flash3_kernel,
                         cudaFuncAttributeMaxDynamicSharedMemorySize, SM_TOTW*4);

    proj_mma_kernel<<<7200, 256, 52736>>>(
        x_l, x_r, ln_l_w, ln_l_b, ln_r_w, ln_r_b,
        wq_l, bq_l, wq_r, bq_r, wv_l, bv_l, wv_r, bv_r);
    fused_flash3_kernel<<<BB*HH, 512, SM_TOTW*4>>>(x_l, x_r, beta, gamma, out_l, out_r);
}

// round 13
// speedup vs baseline: 1.6016x; 1.3886x over previous
#include <cuda_runtime.h>
#include <cstdint>

#define BB   4
#define CCH  64
#define HH   180
#define WWD  320
#define HWP  (HH*WWD)
#define NELT ((size_t)BB*HWP*CCH)

__device__ __forceinline__ uint32_t pack_bf2(float lo, float hi){
    uint32_t u; asm("cvt.rn.bf16x2.f32 %0, %1, %2;" : "=r"(u) : "f"(hi), "f"(lo)); return u;
}
__device__ __forceinline__ uint32_t sptr(const void* p){
    return (uint32_t)__cvta_generic_to_shared(p);
}
__device__ __forceinline__ void mma_bf16(float d[4], const uint32_t a[4], const uint32_t b[2]){
    asm volatile("mma.sync.aligned.m16n8k16.row.col.f32.bf16.bf16.f32 "
                 "{%0,%1,%2,%3}, {%4,%5,%6,%7}, {%8,%9}, {%0,%1,%2,%3};"
                 : "+f"(d[0]), "+f"(d[1]), "+f"(d[2]), "+f"(d[3])
                 : "r"(a[0]), "r"(a[1]), "r"(a[2]), "r"(a[3]), "r"(b[0]), "r"(b[1]));
}
__device__ __forceinline__ void ldsm4(uint32_t r[4], uint32_t a){
    asm volatile("ldmatrix.sync.aligned.m8n8.x4.shared.b16 {%0,%1,%2,%3}, [%4];"
        : "=r"(r[0]), "=r"(r[1]), "=r"(r[2]), "=r"(r[3]) : "r"(a));
}
__device__ __forceinline__ void ldsm4t(uint32_t r[4], uint32_t a){
    asm volatile("ldmatrix.sync.aligned.m8n8.x4.trans.shared.b16 {%0,%1,%2,%3}, [%4];"
        : "=r"(r[0]), "=r"(r[1]), "=r"(r[2]), "=r"(r[3]) : "r"(a));
}
__device__ __forceinline__ void ldsm2t(uint32_t r[2], uint32_t a){
    asm volatile("ldmatrix.sync.aligned.m8n8.x2.trans.shared.b16 {%0,%1}, [%2];"
        : "=r"(r[0]), "=r"(r[1]) : "r"(a));
}

// smem layout (words)
#define SM_CS   0                    // cs[320]
#define SM_RS   320                  // rs[2][64]
#define SM_W    448                  // weight buf [64][36]
#define SM_QL   2752                 // Ql [64][164]
#define SM_QR   13248                // Qr [64][164]
#define SM_VL   23744                // Vl [64][164]
#define SM_VR   34240                // Vr [64][164]
#define SM_X    44736                // xbf [320][36]  (aliased with E [64][164])
#define SM_TOTW 56256                // 225024 bytes

// proj GEMM: Out[o 64][p 320] (bf16, stride 164w) = W[o][c] @ Xb[p][c]^T + bias
__device__ __forceinline__ void proj_gemm(
    const uint32_t* Wb, const uint32_t* Xb, uint32_t* Out, const float* bias,
    int wid, int g, int t, int grp, int r8)
{
    int wyP = wid >> 2, wxP = wid & 3;
    int m0 = wyP * 16;
    float C[10][4];
    #pragma unroll
    for (int nt = 0; nt < 10; nt++)
        #pragma unroll
        for (int k = 0; k < 4; k++) C[nt][k] = 0.f;

    uint32_t aB = sptr(Wb) + (uint32_t)((m0 + r8 + 8*(grp&1))*144 + 16*(grp>>1));
    uint32_t bB = sptr(Xb) + (uint32_t)((wxP*80 + r8 + 8*(grp>>1))*144 + 16*(grp&1));
    #pragma unroll
    for (int ks = 0; ks < 4; ks++) {
        uint32_t a[4];
        ldsm4(a, aB + ks*32);
        #pragma unroll
        for (int j = 0; j < 5; j++) {
            uint32_t bv4[4];
            ldsm4(bv4, bB + j*2304 + ks*32);
            mma_bf16(C[2*j],   a, bv4);
            mma_bf16(C[2*j+1], a, bv4 + 2);
        }
    }
    float b0 = bias[m0 + g], b1 = bias[m0 + g + 8];
    #pragma unroll
    for (int nt = 0; nt < 10; nt++) {
        int w = wxP*40 + nt*4 + t;
        Out[(m0 + g)*164 + w]     = pack_bf2(C[nt][0] + b0, C[nt][1] + b0);
        Out[(m0 + g + 8)*164 + w] = pack_bf2(C[nt][2] + b1, C[nt][3] + b1);
    }
}

__global__ __launch_bounds__(512, 1) void sfam_fused_kernel(
    const float* __restrict__ x_l, const float* __restrict__ x_r,
    const float* __restrict__ lnw_l, const float* __restrict__ lnb_l,
    const float* __restrict__ lnw_r, const float* __restrict__ lnb_r,
    const float* __restrict__ wq_l,  const float* __restrict__ bq_l,
    const float* __restrict__ wq_r,  const float* __restrict__ bq_r,
    const float* __restrict__ wv_l,  const float* __restrict__ bv_l,
    const float* __restrict__ wv_r,  const float* __restrict__ bv_r,
    const float* __restrict__ beta,  const float* __restrict__ gamma,
    float* __restrict__ out_l, float* __restrict__ out_r)
{
    extern __shared__ float sm[];
    float*    cs  = sm + SM_CS;
    float*    rsA = sm + SM_RS;
    uint32_t* Wb  = (uint32_t*)(sm + SM_W);
    uint32_t* Qlw = (uint32_t*)(sm + SM_QL);
    uint32_t* Qrw = (uint32_t*)(sm + SM_QR);
    uint32_t* Vlw = (uint32_t*)(sm + SM_VL);
    uint32_t* Vrw = (uint32_t*)(sm + SM_VR);
    uint32_t* Xb  = (uint32_t*)(sm + SM_X);
    uint32_t* Ew  = (uint32_t*)(sm + SM_X);   // alias: E after proj phase

    int tid = threadIdx.x, lane = tid & 31, wid = tid >> 5;
    int g = lane >> 2, t = lane & 3;
    int grp = lane >> 3, r8 = lane & 7;
    int bh = blockIdx.x, b = bh / HH, h = bh - b * HH;
    size_t cmb = (size_t)b * CCH * HWP + h * WWD;

    if (tid < 320) cs[tid] = 0.f;
    if (tid >= 320 && tid < 448) rsA[tid - 320] = 0.f;

    // ---------------- projection phase (both sides) ----------------
    #pragma unroll 1
    for (int side = 0; side < 2; side++) {
        const float* xrow = (side ? x_r : x_l) + cmb;
        const float* lnw  = side ? lnw_r : lnw_l;
        const float* lnb  = side ? lnb_r : lnb_l;
        const float* wq   = side ? wq_r  : wq_l;
        const float* bq   = side ? bq_r  : bq_l;
        const float* wv   = side ? wv_r  : wv_l;
        const float* bv   = side ? bv_r  : bv_l;
        uint32_t* Qbuf = side ? Qrw : Qlw;
        uint32_t* Vbuf = side ? Vrw : Vlw;

        float mu = 0.f, rsig = 0.f;
        if (tid < 320) {   // stage x (bf16) + LN stats (fp32)
            float s_ = 0.f, ss_ = 0.f;
            #pragma unroll 8
            for (int ci = 0; ci < 32; ci++) {
                float v0 = xrow[(size_t)(2*ci) * HWP + tid];
                float v1 = xrow[(size_t)(2*ci + 1) * HWP + tid];
                s_ += v0 + v1; ss_ += v0*v0 + v1*v1;
                Xb[tid*36 + ci] = pack_bf2(v0, v1);
            }
            float m = s_ * 0.015625f;
            mu = m;
            rsig = rsqrtf(ss_ * 0.015625f - m*m + 1e-6f);
        }
        {   // stage wv -> bf16 [o][c]
            const float2* wsrc = (const float2*)wv;
            #pragma unroll
            for (int i = 0; i < 4; i++) {
                int j = i * 512 + tid;
                float2 w2 = wsrc[j];
                Wb[(j >> 5)*36 + (j & 31)] = pack_bf2(w2.x, w2.y);
            }
        }
        __syncthreads();
        proj_gemm(Wb, Xb, Vbuf, bv, wid, g, t, grp, r8);     // V = wv @ x
        __syncthreads();
        if (tid < 320) {   // normalize x in place
            #pragma unroll 8
            for (int w = 0; w < 32; w++) {
                uint32_t u = Xb[tid*36 + w];
                float lo = __uint_as_float(u << 16);
                float hi = __uint_as_float(u & 0xffff0000u);
                float y0 = (lo - mu) * rsig * lnw[2*w]     + lnb[2*w];
                float y1 = (hi - mu) * rsig * lnw[2*w + 1] + lnb[2*w + 1];
                Xb[tid*36 + w] = pack_bf2(y0, y1);
            }
        }
        {   // stage wq
            const float2* wsrc = (const float2*)wq;
            #pragma unroll
            for (int i = 0; i < 4; i++) {
                int j = i * 512 + tid;
                float2 w2 = wsrc[j];
                Wb[(j >> 5)*36 + (j & 31)] = pack_bf2(w2.x, w2.y);
            }
        }
        __syncthreads();
        proj_gemm(Wb, Xb, Qbuf, bq, wid, g, t, grp, r8);     // Q = wq @ LN(x)
        __syncthreads();
    }

    // ---------------- flash attention phase ----------------
    int wy3 = wid & 1, wx3 = wid >> 1;
    float C3[2][5][4];
    #pragma unroll
    for (int mt = 0; mt < 2; mt++)
        #pragma unroll
        for (int nt = 0; nt < 5; nt++)
            #pragma unroll
            for (int k = 0; k < 4; k++) C3[mt][nt][k] = 0.f;

    #pragma unroll 1
    for (int s = 0; s < 5; s++) {
        int wl0 = s * 64;
        float* rs = rsA + (s & 1) * 64;

        // ---- GEMM1: E = exp(0.125 * Ql_strip^T @ Qr)  (A via ldsm4t on [c][wl]) ----
        {
            int wy1 = wid >> 3, wx1 = wid & 7;
            int m0 = wy1 * 32, n0 = wx1 * 40;
            uint32_t aB  = sptr(Qlw) + (uint32_t)((r8 + 8*(grp&1))*656 + (wl0 + m0 + 8*(grp>>1))*2);
            uint32_t bB  = sptr(Qrw) + (uint32_t)((r8 + 8*(grp&1))*656 + (n0 + 8*(grp>>1))*2);
            uint32_t b2B = sptr(Qrw) + (uint32_t)((r8 + 8*(grp&1))*656 + (n0 + 32)*2);
            float C1[2][5][4];
            #pragma unroll
            for (int mt = 0; mt < 2; mt++)
                #pragma unroll
                for (int nt = 0; nt < 5; nt++)
                    #pragma unroll
                    for (int k = 0; k < 4; k++) C1[mt][nt][k] = 0.f;
            #pragma unroll
            for (int ks = 0; ks < 4; ks++) {
                uint32_t ra[4], rb[4], bb0[4], bb1[4], bb2[2];
                ldsm4t(ra, aB + ks*10496);
                ldsm4t(rb, aB + 32 + ks*10496);
                uint32_t a0[4] = {ra[0], ra[2], ra[1], ra[3]};
                uint32_t a1[4] = {rb[0], rb[2], rb[1], rb[3]};
                ldsm4t(bb0, bB + ks*10496);
                ldsm4t(bb1, bB + 32 + ks*10496);
                ldsm2t(bb2, b2B + ks*10496);
                mma_bf16(C1[0][0], a0, bb0);   mma_bf16(C1[0][1], a0, bb0 + 2);
                mma_bf16(C1[0][2], a0, bb1);   mma_bf16(C1[0][3], a0, bb1 + 2);
                mma_bf16(C1[0][4], a0, bb2);
                mma_bf16(C1[1][0], a1, bb0);   mma_bf16(C1[1][1], a1, bb0 + 2);
                mma_bf16(C1[1][2], a1, bb1);   mma_bf16(C1[1][3], a1, bb1 + 2);
                mma_bf16(C1[1][4], a1, bb2);
            }
            float rsum[2][2];
            rsum[0][0]=rsum[0][1]=rsum[1][0]=rsum[1][1]=0.f;
            #pragma unroll
            for (int nt = 0; nt < 5; nt++) {
                float cv0 = 0.f, cv1 = 0.f;
                #pragma unroll
                for (int mt = 0; mt < 2; mt++) {
                    float e0 = __expf(C1[mt][nt][0]*0.125f);
                    float e1 = __expf(C1[mt][nt][1]*0.125f);
                    float e2 = __expf(C1[mt][nt][2]*0.125f);
                    float e3 = __expf(C1[mt][nt][3]*0.125f);
                    int row = m0 + mt*16 + g;
                    int cw  = wx1*20 + nt*4 + t;
                    Ew[row * 164 + cw]       = pack_bf2(e0, e1);
                    Ew[(row + 8) * 164 + cw] = pack_bf2(e2, e3);
                    rsum[mt][0] += e0 + e1;
                    rsum[mt][1] += e2 + e3;
                    cv0 += e0 + e2;
                    cv1 += e1 + e3;
                }
                cv0 += __shfl_xor_sync(~0u, cv0, 4);
                cv0 += __shfl_xor_sync(~0u, cv0, 8);
                cv0 += __shfl_xor_sync(~0u, cv0, 16);
                cv1 += __shfl_xor_sync(~0u, cv1, 4);
                cv1 += __shfl_xor_sync(~0u, cv1, 8);
                cv1 += __shfl_xor_sync(~0u, cv1, 16);
                if (g == 0) {
                    int col = n0 + nt*8 + 2*t;
                    atomicAdd(&cs[col], cv0);
                    atomicAdd(&cs[col + 1], cv1);
                }
            }
            #pragma unroll
            for (int mt = 0; mt < 2; mt++) {
                float s0 = rsum[mt][0], s1 = rsum[mt][1];
                s0 += __shfl_xor_sync(~0u, s0, 1); s0 += __shfl_xor_sync(~0u, s0, 2);
                s1 += __shfl_xor_sync(~0u, s1, 1); s1 += __shfl_xor_sync(~0u, s1, 2);
                if (t == 0) {
                    atomicAdd(&rs[m0 + mt*16 + g], s0);
                    atomicAdd(&rs[m0 + mt*16 + g + 8], s1);
                }
            }
        }
        __syncthreads();   // (B) E + rs ready

        if (s < 4 && tid < 64) rsA[((s + 1) & 1)*64 + tid] = 0.f;

        // ---- GEMM2': F^T[c][wl] = Vr @ E^T, K=320 ----
        {
            int wy2 = wid >> 2, wx2 = wid & 3;
            int m0 = wy2 * 16, n0 = wx2 * 16;
            uint32_t aBase = sptr(Vrw) + (uint32_t)((m0 + r8 + 8*(grp&1))*656 + 16*(grp>>1));
            uint32_t bBase = sptr(Ew)  + (uint32_t)((n0 + r8 + 8*(grp>>1))*656 + 16*(grp&1));
            float C2[2][4];
            #pragma unroll
            for (int nt = 0; nt < 2; nt++)
                #pragma unroll
                for (int k = 0; k < 4; k++) C2[nt][k] = 0.f;
            #pragma unroll 5
            for (int ks = 0; ks < 20; ks++) {
                uint32_t a[4], bbv[4];
                ldsm4(a, aBase + ks*32);
                ldsm4(bbv, bBase + ks*32);
                mma_bf16(C2[0], a, bbv);
                mma_bf16(C2[1], a, bbv + 2);
            }
            const float* xl = x_l + cmb;
            float* ol = out_l + cmb;
            int c0 = m0 + g;
            float bt0 = beta[c0], bt1 = beta[c0 + 8];
            #pragma unroll
            for (int nt = 0; nt < 2; nt++) {
                int wl = n0 + nt*8 + 2*t;
                float ri0 = __fdividef(1.f, rs[wl]);
                float ri1 = __fdividef(1.f, rs[wl + 1]);
                float2 x0 = *(const float2*)(xl + (size_t)c0*HWP + wl0 + wl);
                *(float2*)(ol + (size_t)c0*HWP + wl0 + wl) = make_float2(
                    x0.x + bt0*ri0*C2[nt][0], x0.y + bt0*ri1*C2[nt][1]);
                float2 x1 = *(const float2*)(xl + (size_t)(c0+8)*HWP + wl0 + wl);
                *(float2*)(ol + (size_t)(c0+8)*HWP + wl0 + wl) = make_float2(
                    x1.x + bt1*ri0*C2[nt][2], x1.y + bt1*ri1*C2[nt][3]);
            }
        }

        // ---- GEMM3: C3 += Vl[:, strip] @ E ----
        {
            int m0 = wy3 * 32, n0 = wx3 * 40;
            uint32_t aBase  = sptr(Vlw) + (uint32_t)((m0 + r8 + 8*(grp&1))*656 + wl0*2 + 16*(grp>>1));
            uint32_t bBase  = sptr(Ew) + (uint32_t)((r8 + 8*(grp&1))*656 + (n0 + 8*(grp>>1))*2);
            uint32_t b2Base = sptr(Ew) + (uint32_t)((r8 + 8*(grp&1))*656 + (n0 + 32)*2);
            #pragma unroll
            for (int ks = 0; ks < 4; ks++) {
                uint32_t a0[4], a1[4], bb0[4], bb1[4], bb2[2];
                ldsm4(a0, aBase + ks*32);
                ldsm4(a1, aBase + 16*656 + ks*32);
                ldsm4t(bb0, bBase + ks*10496);
                ldsm4t(bb1, bBase + 32 + ks*10496);
                ldsm2t(bb2, b2Base + ks*10496);
                mma_bf16(C3[0][0], a0, bb0);   mma_bf16(C3[0][1], a0, bb0 + 2);
                mma_bf16(C3[0][2], a0, bb1);   mma_bf16(C3[0][3], a0, bb1 + 2);
                mma_bf16(C3[0][4], a0, bb2);
                mma_bf16(C3[1][0], a1, bb0);   mma_bf16(C3[1][1], a1, bb0 + 2);
                mma_bf16(C3[1][2], a1, bb1);   mma_bf16(C3[1][3], a1, bb1 + 2);
                mma_bf16(C3[1][4], a1, bb2);
            }
        }
        __syncthreads();   // (C) strip done; E free
    }

    if (tid < 320) cs[tid] = __fdividef(1.f, cs[tid]);
    __syncthreads();

    {   // out_r = x_r + gamma * (C3 * cinv)
        const float* xr = x_r + cmb;
        float* orr = out_r + cmb;
        int m0 = wy3 * 32, n0 = wx3 * 40;
        #pragma unroll
        for (int mt = 0; mt < 2; mt++) {
            int c0 = m0 + mt*16 + g;
            float g0 = gamma[c0], g1 = gamma[c0 + 8];
            #pragma unroll
            for (int nt = 0; nt < 5; nt++) {
                int col = n0 + nt*8 + 2*t;
                float ci0 = cs[col], ci1 = cs[col + 1];
                float2 x0 = *(const float2*)(xr + (size_t)c0*HWP + col);
                *(float2*)(orr + (size_t)c0*HWP + col) = make_float2(
                    x0.x + g0*ci0*C3[mt][nt][0], x0.y + g0*ci1*C3[mt][nt][1]);
                float2 x1 = *(const float2*)(xr + (size_t)(c0+8)*HWP + col);
                *(float2*)(orr + (size_t)(c0+8)*HWP + col) = make_float2(
                    x1.x + g1*ci0*C3[mt][nt][2], x1.y + g1*ci1*C3[mt][nt][3]);
            }
        }
    }
}

extern "C" void kernel_launch(void* const* d_in, const int* in_sizes, int n_in,
                              void* d_out, int out_size)
{
    const float* x_l    = (const float*)d_in[0];
    const float* x_r    = (const float*)d_in[1];
    const float* ln_l_w = (const float*)d_in[2];
    const float* ln_l_b = (const float*)d_in[3];
    const float* ln_r_w = (const float*)d_in[4];
    const float* ln_r_b = (const float*)d_in[5];
    const float* wq_l   = (const float*)d_in[6];
    const float* bq_l   = (const float*)d_in[7];
    const float* wq_r   = (const float*)d_in[8];
    const float* bq_r   = (const float*)d_in[9];
    const float* wv_l   = (const float*)d_in[10];
    const float* bv_l   = (const float*)d_in[11];
    const float* wv_r   = (const float*)d_in[12];
    const float* bv_r   = (const float*)d_in[13];
    const float* beta   = (const float*)d_in[14];
    const float* gamma  = (const float*)d_in[15];

    float* out_l = (float*)d_out;
    float* out_r = out_l + NELT;

    cudaFuncSetAttribute(sfam_fused_kernel,
                         cudaFuncAttributeMaxDynamicSharedMemorySize, SM_TOTW*4);

    sfam_fused_kernel<<<BB*HH, 512, SM_TOTW*4>>>(
        x_l, x_r, ln_l_w, ln_l_b, ln_r_w, ln_r_b,
        wq_l, bq_l, wq_r, bq_r, wv_l, bv_l, wv_r, bv_r,
        beta, gamma, out_l, out_r);
}